// round 3
// baseline (speedup 1.0000x reference)
#include <cuda_runtime.h>
#include <cstdint>

#define SLOPE 0.1f
#define EPS 1e-5f

constexpr int B   = 2;
constexpr int N   = 40960;
constexpr int K   = 16;
constexpr int C   = 64;
constexpr int CIN = 74;   // C + 10 rel features
constexpr int CINP = 75;  // padded stride (conflict-free)
constexpr int OUT = 64;
constexpr int SLOTS = 32; // atomic slot spreading for BN partials
constexpr int PPB1 = 16;  // points per block, kernel 1
constexpr int PPB3 = 16;  // points per block, kernel 3

// ---------------- device scratch (static; no allocation) ----------------
__device__ float g_featT[(size_t)B * N * C];            // 21 MB  (B,N,C)
__device__ float g_z1[(size_t)B * N * K * OUT];         // 320 MiB pre-BN mlp1 out, [pt][o][k]
__device__ float g_bn1s[SLOTS][OUT];
__device__ float g_bn1q[SLOTS][OUT];
__device__ float g_bn2s[SLOTS][OUT];
__device__ float g_bn2q[SLOTS][OUT];
__device__ float g_scale1[OUT], g_bias1[OUT];
__device__ float g_scale2[OUT], g_bias2[OUT];

// ---------------- kernel: zero BN partial accumulators ----------------
__global__ void k_zero() {
    int t = blockIdx.x * blockDim.x + threadIdx.x;
    if (t < SLOTS * OUT) {
        ((float*)g_bn1s)[t] = 0.f;
        ((float*)g_bn1q)[t] = 0.f;
        ((float*)g_bn2s)[t] = 0.f;
        ((float*)g_bn2q)[t] = 0.f;
    }
}

// ---------------- kernel: transpose feat (B,C,N) -> (B,N,C) ----------------
__global__ void k_trans(const float* __restrict__ feat) {
    __shared__ float tile[32][33];
    int b  = blockIdx.z;
    int c0 = blockIdx.y * 32;
    int n0 = blockIdx.x * 32;
    int tx = threadIdx.x, ty = threadIdx.y;
    #pragma unroll
    for (int j = ty; j < 32; j += 8)
        tile[j][tx] = feat[((size_t)b * C + (c0 + j)) * N + (n0 + tx)];
    __syncthreads();
    #pragma unroll
    for (int j = ty; j < 32; j += 8)
        g_featT[((size_t)b * N + (n0 + j)) * C + (c0 + tx)] = tile[tx][j];
}

// ---------------- kernel 1: gather + rel + W1 GEMM + BN1 stats ----------------
__global__ void __launch_bounds__(128) k1(const float* __restrict__ xyz,
                                          const int*   __restrict__ nidx,
                                          const float* __restrict__ W1) {
    __shared__ float W1s[OUT * CINP];       // 19.2 KB
    __shared__ float Xs[2][K * CINP];       // 9.6 KB  (two points of a pair)
    __shared__ int   idxs[2][K];
    __shared__ float ctr[2][3];

    const int t   = threadIdx.x;
    const int blk = blockIdx.x;
    const int blocksPerBatch = N / PPB1;          // 2560
    const int b  = blk / blocksPerBatch;
    const int n0 = (blk % blocksPerBatch) * PPB1;

    // load W1 into padded smem
    for (int i = t; i < OUT * CIN; i += 128) {
        int o = i / CIN, c = i % CIN;
        W1s[o * CINP + c] = W1[i];
    }

    // thread tiling: 64 threads per point of the pair; 4(o) x 4(k) outputs each
    const int p_loc = t >> 6;          // 0/1 point within pair
    const int tt    = t & 63;
    const int kg    = tt & 3;          // lane&3 -> shuffle groups of 4
    const int og    = tt >> 2;         // 0..15
    const int obase = og * 4;
    const int kbase = kg * 4;

    float accS0 = 0.f, accS1 = 0.f, accS2 = 0.f, accS3 = 0.f;
    float accQ0 = 0.f, accQ1 = 0.f, accQ2 = 0.f, accQ3 = 0.f;

    for (int pair = 0; pair < PPB1 / 2; ++pair) {
        __syncthreads();   // previous pair's Xs fully consumed
        if (t < 32) {
            int pp = t >> 4, k = t & 15;
            int n  = n0 + pair * 2 + pp;
            idxs[pp][k] = nidx[((size_t)b * N + n) * K + k];
        }
        if (t >= 32 && t < 40) {
            int pp = (t - 32) >> 2, d = (t - 32) & 3;
            if (d < 3) {
                int n = n0 + pair * 2 + pp;
                ctr[pp][d] = xyz[((size_t)b * N + n) * 3 + d];
            }
        }
        __syncthreads();
        // coalesced gather of neighbor features via transposed feat
        for (int i = t; i < 2 * K * C; i += 128) {
            int pp = i >> 10;
            int k  = (i >> 6) & (K - 1);
            int c  = i & (C - 1);
            Xs[pp][k * CINP + c] = g_featT[((size_t)b * N + idxs[pp][k]) * C + c];
        }
        // relative position encoding (10 channels)
        if (t < 32) {
            int pp = t >> 4, k = t & 15;
            int nb = idxs[pp][k];
            float nx = xyz[((size_t)b * N + nb) * 3 + 0];
            float ny = xyz[((size_t)b * N + nb) * 3 + 1];
            float nz = xyz[((size_t)b * N + nb) * 3 + 2];
            float cx = ctr[pp][0], cy = ctr[pp][1], cz = ctr[pp][2];
            float dx = cx - nx, dy = cy - ny, dz = cz - nz;
            float dist = sqrtf(dx * dx + dy * dy + dz * dz);
            float* xr = &Xs[pp][k * CINP + C];
            xr[0] = dx; xr[1] = dy; xr[2] = dz; xr[3] = dist;
            xr[4] = cx; xr[5] = cy; xr[6] = cz;
            xr[7] = nx; xr[8] = ny; xr[9] = nz;
        }
        __syncthreads();

        // 4x4 tile GEMM: z[o][k] = sum_c W1[o][c] * X[c][k]
        float acc[4][4];
        #pragma unroll
        for (int a = 0; a < 4; ++a)
            #pragma unroll
            for (int bb = 0; bb < 4; ++bb) acc[a][bb] = 0.f;

        const float* Xp = Xs[p_loc];
        const int kb = kbase * CINP;
        const int wb = obase * CINP;
        for (int c = 0; c < CIN; ++c) {
            float x0 = Xp[kb + 0 * CINP + c];
            float x1 = Xp[kb + 1 * CINP + c];
            float x2 = Xp[kb + 2 * CINP + c];
            float x3 = Xp[kb + 3 * CINP + c];
            #pragma unroll
            for (int jo = 0; jo < 4; ++jo) {
                float w = W1s[wb + jo * CINP + c];
                acc[jo][0] = fmaf(w, x0, acc[jo][0]);
                acc[jo][1] = fmaf(w, x1, acc[jo][1]);
                acc[jo][2] = fmaf(w, x2, acc[jo][2]);
                acc[jo][3] = fmaf(w, x3, acc[jo][3]);
            }
        }

        // store z1 [pt][o][k] with float4, accumulate BN1 partial stats
        int n = n0 + pair * 2 + p_loc;
        size_t ptbase = ((size_t)(b * N + n)) * (size_t)(OUT * K);
        #pragma unroll
        for (int jo = 0; jo < 4; ++jo) {
            int o = obase + jo;
            float4 v = make_float4(acc[jo][0], acc[jo][1], acc[jo][2], acc[jo][3]);
            *(float4*)&g_z1[ptbase + (size_t)o * K + kbase] = v;
            float s = acc[jo][0] + acc[jo][1] + acc[jo][2] + acc[jo][3];
            float q = acc[jo][0] * acc[jo][0] + acc[jo][1] * acc[jo][1]
                    + acc[jo][2] * acc[jo][2] + acc[jo][3] * acc[jo][3];
            if (jo == 0) { accS0 += s; accQ0 += q; }
            else if (jo == 1) { accS1 += s; accQ1 += q; }
            else if (jo == 2) { accS2 += s; accQ2 += q; }
            else { accS3 += s; accQ3 += q; }
        }
    }

    // reduce over the 4-lane k-groups, then slotted atomics
    #pragma unroll
    for (int off = 1; off <= 2; off <<= 1) {
        accS0 += __shfl_xor_sync(0xffffffffu, accS0, off);
        accQ0 += __shfl_xor_sync(0xffffffffu, accQ0, off);
        accS1 += __shfl_xor_sync(0xffffffffu, accS1, off);
        accQ1 += __shfl_xor_sync(0xffffffffu, accQ1, off);
        accS2 += __shfl_xor_sync(0xffffffffu, accS2, off);
        accQ2 += __shfl_xor_sync(0xffffffffu, accQ2, off);
        accS3 += __shfl_xor_sync(0xffffffffu, accS3, off);
        accQ3 += __shfl_xor_sync(0xffffffffu, accQ3, off);
    }
    if (kg == 0) {
        int slot = blk & (SLOTS - 1);
        atomicAdd(&g_bn1s[slot][obase + 0], accS0);
        atomicAdd(&g_bn1q[slot][obase + 0], accQ0);
        atomicAdd(&g_bn1s[slot][obase + 1], accS1);
        atomicAdd(&g_bn1q[slot][obase + 1], accQ1);
        atomicAdd(&g_bn1s[slot][obase + 2], accS2);
        atomicAdd(&g_bn1q[slot][obase + 2], accQ2);
        atomicAdd(&g_bn1s[slot][obase + 3], accS3);
        atomicAdd(&g_bn1q[slot][obase + 3], accQ3);
    }
}

// ---------------- BN finalize kernels: reference globals DIRECTLY ----------------
__global__ void k_bnfin1(const float* __restrict__ g, const float* __restrict__ bb) {
    int o = threadIdx.x;
    float s = 0.f, q = 0.f;
    #pragma unroll
    for (int sl = 0; sl < SLOTS; ++sl) { s += g_bn1s[sl][o]; q += g_bn1q[sl][o]; }
    const float cnt = (float)((size_t)B * N * K);
    float mean = s / cnt;
    float var  = q / cnt - mean * mean;
    float rstd = rsqrtf(var + EPS);
    g_scale1[o] = rstd * g[o];
    g_bias1[o]  = bb[o] - mean * rstd * g[o];
}

__global__ void k_bnfin2(const float* __restrict__ g, const float* __restrict__ bb) {
    int o = threadIdx.x;
    float s = 0.f, q = 0.f;
    #pragma unroll
    for (int sl = 0; sl < SLOTS; ++sl) { s += g_bn2s[sl][o]; q += g_bn2q[sl][o]; }
    const float cnt = (float)((size_t)B * N);
    float mean = s / cnt;
    float var  = q / cnt - mean * mean;
    float rstd = rsqrtf(var + EPS);
    g_scale2[o] = rstd * g[o];
    g_bias2[o]  = bb[o] - mean * rstd * g[o];
}

// ---------------- kernel 3: BN1+lrelu, score GEMM, softmax-pool, Wm ----------------
__global__ void __launch_bounds__(128) k3(const float* __restrict__ Ws,
                                          const float* __restrict__ Wm,
                                          float* __restrict__ out) {
    __shared__ float Wss[OUT * 65];     // 16.6 KB
    __shared__ float Wms[OUT * 65];     // 16.6 KB
    __shared__ float x1s[2][K * 65];    // 8.3 KB
    __shared__ float ps[2][OUT];
    __shared__ float scl[OUT], bia[OUT];

    const int t   = threadIdx.x;
    const int blk = blockIdx.x;
    const int blocksPerBatch = N / PPB3;
    const int b  = blk / blocksPerBatch;
    const int n0 = (blk % blocksPerBatch) * PPB3;

    for (int i = t; i < OUT * OUT; i += 128) {
        int o = i >> 6, c = i & 63;
        Wss[o * 65 + c] = Ws[i];
        Wms[o * 65 + c] = Wm[i];
    }
    if (t < OUT) { scl[t] = g_scale1[t]; bia[t] = g_bias1[t]; }

    const int p_loc = t >> 6;
    const int tt    = t & 63;
    const int kg    = tt & 3;
    const int og    = tt >> 2;
    const int obase = og * 4;
    const int kbase = kg * 4;

    float a2s = 0.f, a2q = 0.f;

    for (int pair = 0; pair < PPB3 / 2; ++pair) {
        __syncthreads();
        // load z1 for 2 points, apply BN1 + LeakyReLU -> x1s
        const float4* src = (const float4*)&g_z1[((size_t)(b * N + n0 + pair * 2)) * (size_t)(OUT * K)];
        for (int j = t; j < 512; j += 128) {
            int pp = j >> 8;
            int r  = j & 255;
            int o  = r >> 2;
            int kq = (r & 3) * 4;
            float4 v = src[j];
            float s = scl[o], bs = bia[o];
            float y0 = fmaf(v.x, s, bs); y0 = y0 >= 0.f ? y0 : SLOPE * y0;
            float y1 = fmaf(v.y, s, bs); y1 = y1 >= 0.f ? y1 : SLOPE * y1;
            float y2 = fmaf(v.z, s, bs); y2 = y2 >= 0.f ? y2 : SLOPE * y2;
            float y3 = fmaf(v.w, s, bs); y3 = y3 >= 0.f ? y3 : SLOPE * y3;
            x1s[pp][(kq + 0) * 65 + o] = y0;
            x1s[pp][(kq + 1) * 65 + o] = y1;
            x1s[pp][(kq + 2) * 65 + o] = y2;
            x1s[pp][(kq + 3) * 65 + o] = y3;
        }
        __syncthreads();

        // score GEMM: S[o][k] = sum_c Ws[o][c] * x1[c][k]   (x1s stored [k][c] padded)
        float sc[4][4];
        #pragma unroll
        for (int a = 0; a < 4; ++a)
            #pragma unroll
            for (int b2 = 0; b2 < 4; ++b2) sc[a][b2] = 0.f;
        const float* Xp = x1s[p_loc];
        const int kb = kbase * 65;
        const int wb = obase * 65;
        for (int c = 0; c < OUT; ++c) {
            float x0 = Xp[kb + 0 * 65 + c];
            float x1 = Xp[kb + 1 * 65 + c];
            float x2 = Xp[kb + 2 * 65 + c];
            float x3 = Xp[kb + 3 * 65 + c];
            #pragma unroll
            for (int jo = 0; jo < 4; ++jo) {
                float w = Wss[wb + jo * 65 + c];
                sc[jo][0] = fmaf(w, x0, sc[jo][0]);
                sc[jo][1] = fmaf(w, x1, sc[jo][1]);
                sc[jo][2] = fmaf(w, x2, sc[jo][2]);
                sc[jo][3] = fmaf(w, x3, sc[jo][3]);
            }
        }

        // softmax over K (16 values spread across 4 lanes x 4 regs) + pooling
        #pragma unroll
        for (int jo = 0; jo < 4; ++jo) {
            int o = obase + jo;
            float m = fmaxf(fmaxf(sc[jo][0], sc[jo][1]), fmaxf(sc[jo][2], sc[jo][3]));
            m = fmaxf(m, __shfl_xor_sync(0xffffffffu, m, 1));
            m = fmaxf(m, __shfl_xor_sync(0xffffffffu, m, 2));
            float e0 = __expf(sc[jo][0] - m);
            float e1 = __expf(sc[jo][1] - m);
            float e2 = __expf(sc[jo][2] - m);
            float e3 = __expf(sc[jo][3] - m);
            float den = e0 + e1 + e2 + e3;
            float num = e0 * Xp[kb + 0 * 65 + o]
                      + e1 * Xp[kb + 1 * 65 + o]
                      + e2 * Xp[kb + 2 * 65 + o]
                      + e3 * Xp[kb + 3 * 65 + o];
            den += __shfl_xor_sync(0xffffffffu, den, 1);
            num += __shfl_xor_sync(0xffffffffu, num, 1);
            den += __shfl_xor_sync(0xffffffffu, den, 2);
            num += __shfl_xor_sync(0xffffffffu, num, 2);
            if (kg == 0) ps[p_loc][o] = num / den;
        }
        __syncthreads();

        // z2 = Wm @ p  (one (point, channel) per thread)
        {
            int o  = t & 63;
            int pp = t >> 6;
            float z2 = 0.f;
            #pragma unroll 8
            for (int c = 0; c < OUT; ++c)
                z2 = fmaf(Wms[o * 65 + c], ps[pp][c], z2);
            int n = n0 + pair * 2 + pp;
            out[((size_t)b * OUT + o) * N + n] = z2;   // raw pre-BN2
            a2s += z2;
            a2q += z2 * z2;
        }
    }

    int slot = blk & (SLOTS - 1);
    atomicAdd(&g_bn2s[slot][t & 63], a2s);
    atomicAdd(&g_bn2q[slot][t & 63], a2q);
}

// ---------------- kernel 5: apply BN2 + LeakyReLU in place ----------------
__global__ void k5(float* __restrict__ out) {
    int i = blockIdx.x * blockDim.x + threadIdx.x;
    if (i < B * OUT * N) {
        int o = (i / N) & (OUT - 1);
        float v = fmaf(out[i], g_scale2[o], g_bias2[o]);
        out[i] = v >= 0.f ? v : SLOPE * v;
    }
}

// ---------------- launch ----------------
extern "C" void kernel_launch(void* const* d_in, const int* in_sizes, int n_in,
                              void* d_out, int out_size) {
    const float* xyz  = (const float*)d_in[0];
    const float* feat = (const float*)d_in[1];
    const int*   nidx = (const int*)d_in[2];
    const float* W1   = (const float*)d_in[3];
    const float* g1   = (const float*)d_in[4];
    const float* b1   = (const float*)d_in[5];
    const float* Ws   = (const float*)d_in[6];
    const float* Wm   = (const float*)d_in[7];
    const float* g2   = (const float*)d_in[8];
    const float* b2   = (const float*)d_in[9];
    float* out = (float*)d_out;

    k_zero<<<(SLOTS * OUT + 255) / 256, 256>>>();
    k_trans<<<dim3(N / 32, C / 32, B), dim3(32, 8)>>>(feat);
    k1<<<B * N / PPB1, 128>>>(xyz, nidx, W1);
    k_bnfin1<<<1, OUT>>>(g1, b1);
    k3<<<B * N / PPB3, 128>>>(Ws, Wm, out);
    k_bnfin2<<<1, OUT>>>(g2, b2);
    k5<<<(B * OUT * N + 255) / 256, 256>>>(out);
}

// round 4
// speedup vs baseline: 1.1184x; 1.1184x over previous
#include <cuda_runtime.h>
#include <cstdint>

#define SLOPE 0.1f
#define EPS 1e-5f

constexpr int B   = 2;
constexpr int N   = 40960;
constexpr int K   = 16;
constexpr int C   = 64;
constexpr int CIN = 74;    // C + 10 rel features
constexpr int XST = 18;    // Xs row stride in floats ([c][k] layout, 8B-aligned, low conflict)
constexpr int WST = 68;    // transposed weight stride ([c][o] layout, 16B-aligned)
constexpr int OUT = 64;
constexpr int SLOTS = 32;
constexpr int PPB1 = 16;
constexpr int PPB3 = 16;

// ---------------- device scratch (static; no allocation) ----------------
__device__ float g_featT[(size_t)B * N * C];
__device__ float g_z1[(size_t)B * N * K * OUT];      // pre-BN mlp1 out, [pt][o][k]
__device__ float g_bn1s[SLOTS][OUT];
__device__ float g_bn1q[SLOTS][OUT];
__device__ float g_bn2s[SLOTS][OUT];
__device__ float g_bn2q[SLOTS][OUT];
__device__ float g_scale1[OUT], g_bias1[OUT];
__device__ float g_scale2[OUT], g_bias2[OUT];

// -------- packed f32x2 helpers --------
__device__ __forceinline__ void fma2(unsigned long long& acc,
                                     unsigned long long a, unsigned long long b) {
    asm("fma.rn.f32x2 %0, %1, %2, %0;" : "+l"(acc) : "l"(a), "l"(b));
}
__device__ __forceinline__ unsigned long long dup2(float w) {
    unsigned long long r;
    asm("mov.b64 %0, {%1, %1};" : "=l"(r) : "f"(w));
    return r;
}
__device__ __forceinline__ void unpack2(unsigned long long v, float& lo, float& hi) {
    asm("mov.b64 {%0, %1}, %2;" : "=f"(lo), "=f"(hi) : "l"(v));
}

// ---------------- zero BN partials ----------------
__global__ void k_zero() {
    int t = blockIdx.x * blockDim.x + threadIdx.x;
    if (t < SLOTS * OUT) {
        ((float*)g_bn1s)[t] = 0.f;
        ((float*)g_bn1q)[t] = 0.f;
        ((float*)g_bn2s)[t] = 0.f;
        ((float*)g_bn2q)[t] = 0.f;
    }
}

// ---------------- transpose feat (B,C,N) -> (B,N,C) ----------------
__global__ void k_trans(const float* __restrict__ feat) {
    __shared__ float tile[32][33];
    int b  = blockIdx.z;
    int c0 = blockIdx.y * 32;
    int n0 = blockIdx.x * 32;
    int tx = threadIdx.x, ty = threadIdx.y;
    #pragma unroll
    for (int j = ty; j < 32; j += 8)
        tile[j][tx] = feat[((size_t)b * C + (c0 + j)) * N + (n0 + tx)];
    __syncthreads();
    #pragma unroll
    for (int j = ty; j < 32; j += 8)
        g_featT[((size_t)b * N + (n0 + j)) * C + (c0 + tx)] = tile[tx][j];
}

// ---------------- kernel 1: gather + rel + W1 GEMM (FFMA2) + BN1 stats ----------------
__global__ void __launch_bounds__(128) k1(const float* __restrict__ xyz,
                                          const int*   __restrict__ nidx,
                                          const float* __restrict__ W1) {
    __shared__ __align__(16) float W1t[CIN * WST];     // [c][o] 20.1 KB
    __shared__ __align__(16) float Xs[2][CIN * XST];   // [c][k] 10.7 KB
    __shared__ int   idxs[2][K];
    __shared__ float ctr[2][3];

    const int t   = threadIdx.x;
    const int blk = blockIdx.x;
    const int blocksPerBatch = N / PPB1;
    const int b  = blk / blocksPerBatch;
    const int n0 = (blk % blocksPerBatch) * PPB1;

    // W1 [o][c] row-major -> W1t [c][o]; coalesced global read
    for (int i = t; i < OUT * CIN; i += 128) {
        int o = i / CIN, c = i % CIN;
        W1t[c * WST + o] = W1[i];
    }

    const int p_loc = t >> 6;          // point within pair
    const int tt    = t & 63;
    const int kg    = tt & 3;
    const int og    = tt >> 2;
    const int obase = og * 4;
    const int kbase = kg * 4;

    float accS0 = 0.f, accS1 = 0.f, accS2 = 0.f, accS3 = 0.f;
    float accQ0 = 0.f, accQ1 = 0.f, accQ2 = 0.f, accQ3 = 0.f;

    for (int pair = 0; pair < PPB1 / 2; ++pair) {
        __syncthreads();
        if (t < 32) {
            int pp = t >> 4, k = t & 15;
            int n  = n0 + pair * 2 + pp;
            idxs[pp][k] = nidx[((size_t)b * N + n) * K + k];
        }
        if (t >= 32 && t < 40) {
            int pp = (t - 32) >> 2, d = (t - 32) & 3;
            if (d < 3) {
                int n = n0 + pair * 2 + pp;
                ctr[pp][d] = xyz[((size_t)b * N + n) * 3 + d];
            }
        }
        __syncthreads();
        // gather neighbor feats -> Xs[c][k] (coalesced global reads)
        for (int i = t; i < 2 * K * C; i += 128) {
            int pp = i >> 10;
            int k  = (i >> 6) & (K - 1);
            int c  = i & (C - 1);
            Xs[pp][c * XST + k] = g_featT[((size_t)b * N + idxs[pp][k]) * C + c];
        }
        // relative position encoding (channels C..C+9)
        if (t < 32) {
            int pp = t >> 4, k = t & 15;
            int nb = idxs[pp][k];
            float nx = xyz[((size_t)b * N + nb) * 3 + 0];
            float ny = xyz[((size_t)b * N + nb) * 3 + 1];
            float nz = xyz[((size_t)b * N + nb) * 3 + 2];
            float cx = ctr[pp][0], cy = ctr[pp][1], cz = ctr[pp][2];
            float dx = cx - nx, dy = cy - ny, dz = cz - nz;
            float dist = sqrtf(dx * dx + dy * dy + dz * dz);
            float* X = Xs[pp];
            X[(C + 0) * XST + k] = dx;  X[(C + 1) * XST + k] = dy;
            X[(C + 2) * XST + k] = dz;  X[(C + 3) * XST + k] = dist;
            X[(C + 4) * XST + k] = cx;  X[(C + 5) * XST + k] = cy;
            X[(C + 6) * XST + k] = cz;  X[(C + 7) * XST + k] = nx;
            X[(C + 8) * XST + k] = ny;  X[(C + 9) * XST + k] = nz;
        }
        __syncthreads();

        // packed 4(o) x 4(k) GEMM via fma.rn.f32x2
        unsigned long long aL[4] = {0ull, 0ull, 0ull, 0ull};  // (k0,k1)
        unsigned long long aH[4] = {0ull, 0ull, 0ull, 0ull};  // (k2,k3)
        const float* Xp = Xs[p_loc];
        #pragma unroll 2
        for (int c = 0; c < CIN; ++c) {
            unsigned long long x01 = *(const unsigned long long*)&Xp[c * XST + kbase];
            unsigned long long x23 = *(const unsigned long long*)&Xp[c * XST + kbase + 2];
            float4 w = *(const float4*)&W1t[c * WST + obase];
            unsigned long long w0 = dup2(w.x), w1 = dup2(w.y), w2 = dup2(w.z), w3 = dup2(w.w);
            fma2(aL[0], w0, x01); fma2(aH[0], w0, x23);
            fma2(aL[1], w1, x01); fma2(aH[1], w1, x23);
            fma2(aL[2], w2, x01); fma2(aH[2], w2, x23);
            fma2(aL[3], w3, x01); fma2(aH[3], w3, x23);
        }

        // unpack, store z1 [pt][o][k] float4, accumulate BN1 stats
        int n = n0 + pair * 2 + p_loc;
        size_t ptbase = ((size_t)(b * N + n)) * (size_t)(OUT * K);
        #pragma unroll
        for (int jo = 0; jo < 4; ++jo) {
            float v0, v1, v2, v3;
            unpack2(aL[jo], v0, v1);
            unpack2(aH[jo], v2, v3);
            int o = obase + jo;
            *(float4*)&g_z1[ptbase + (size_t)o * K + kbase] = make_float4(v0, v1, v2, v3);
            float s = v0 + v1 + v2 + v3;
            float q = v0 * v0 + v1 * v1 + v2 * v2 + v3 * v3;
            if (jo == 0) { accS0 += s; accQ0 += q; }
            else if (jo == 1) { accS1 += s; accQ1 += q; }
            else if (jo == 2) { accS2 += s; accQ2 += q; }
            else { accS3 += s; accQ3 += q; }
        }
    }

    #pragma unroll
    for (int off = 1; off <= 2; off <<= 1) {
        accS0 += __shfl_xor_sync(0xffffffffu, accS0, off);
        accQ0 += __shfl_xor_sync(0xffffffffu, accQ0, off);
        accS1 += __shfl_xor_sync(0xffffffffu, accS1, off);
        accQ1 += __shfl_xor_sync(0xffffffffu, accQ1, off);
        accS2 += __shfl_xor_sync(0xffffffffu, accS2, off);
        accQ2 += __shfl_xor_sync(0xffffffffu, accQ2, off);
        accS3 += __shfl_xor_sync(0xffffffffu, accS3, off);
        accQ3 += __shfl_xor_sync(0xffffffffu, accQ3, off);
    }
    if (kg == 0) {
        int slot = blk & (SLOTS - 1);
        atomicAdd(&g_bn1s[slot][obase + 0], accS0);
        atomicAdd(&g_bn1q[slot][obase + 0], accQ0);
        atomicAdd(&g_bn1s[slot][obase + 1], accS1);
        atomicAdd(&g_bn1q[slot][obase + 1], accQ1);
        atomicAdd(&g_bn1s[slot][obase + 2], accS2);
        atomicAdd(&g_bn1q[slot][obase + 2], accQ2);
        atomicAdd(&g_bn1s[slot][obase + 3], accS3);
        atomicAdd(&g_bn1q[slot][obase + 3], accQ3);
    }
}

// ---------------- BN finalize (globals referenced directly) ----------------
__global__ void k_bnfin1(const float* __restrict__ g, const float* __restrict__ bb) {
    int o = threadIdx.x;
    float s = 0.f, q = 0.f;
    #pragma unroll
    for (int sl = 0; sl < SLOTS; ++sl) { s += g_bn1s[sl][o]; q += g_bn1q[sl][o]; }
    const float cnt = (float)((size_t)B * N * K);
    float mean = s / cnt;
    float var  = q / cnt - mean * mean;
    float rstd = rsqrtf(var + EPS);
    g_scale1[o] = rstd * g[o];
    g_bias1[o]  = bb[o] - mean * rstd * g[o];
}

__global__ void k_bnfin2(const float* __restrict__ g, const float* __restrict__ bb) {
    int o = threadIdx.x;
    float s = 0.f, q = 0.f;
    #pragma unroll
    for (int sl = 0; sl < SLOTS; ++sl) { s += g_bn2s[sl][o]; q += g_bn2q[sl][o]; }
    const float cnt = (float)((size_t)B * N);
    float mean = s / cnt;
    float var  = q / cnt - mean * mean;
    float rstd = rsqrtf(var + EPS);
    g_scale2[o] = rstd * g[o];
    g_bias2[o]  = bb[o] - mean * rstd * g[o];
}

// ---------------- kernel 3: BN1+lrelu, score GEMM (FFMA2), softmax-pool, Wm ----------------
__global__ void __launch_bounds__(128) k3(const float* __restrict__ Ws,
                                          const float* __restrict__ Wm,
                                          float* __restrict__ out) {
    __shared__ __align__(16) float Wst[OUT * WST];     // Ws^T [c][o] 17.4 KB
    __shared__ float Wms[OUT * 65];                    // Wm [o][c] 16.6 KB
    __shared__ __align__(16) float x1s[2][OUT * XST];  // x1 [c][k] 9.2 KB
    __shared__ float ps[2][OUT];
    __shared__ float scl[OUT], bia[OUT];

    const int t   = threadIdx.x;
    const int blk = blockIdx.x;
    const int blocksPerBatch = N / PPB3;
    const int b  = blk / blocksPerBatch;
    const int n0 = (blk % blocksPerBatch) * PPB3;

    for (int i = t; i < OUT * OUT; i += 128) {
        int o = i >> 6, c = i & 63;
        Wst[c * WST + o] = Ws[i];
        Wms[o * 65 + c]  = Wm[i];
    }
    if (t < OUT) { scl[t] = g_scale1[t]; bia[t] = g_bias1[t]; }

    const int p_loc = t >> 6;
    const int tt    = t & 63;
    const int kg    = tt & 3;
    const int og    = tt >> 2;
    const int obase = og * 4;
    const int kbase = kg * 4;

    float a2s = 0.f, a2q = 0.f;

    for (int pair = 0; pair < PPB3 / 2; ++pair) {
        __syncthreads();
        // z1 load (float4, coalesced) + BN1 + LeakyReLU -> x1s[c][k]
        const float4* src = (const float4*)&g_z1[((size_t)(b * N + n0 + pair * 2)) * (size_t)(OUT * K)];
        for (int j = t; j < 512; j += 128) {
            int pp = j >> 8;
            int r  = j & 255;
            int o  = r >> 2;
            int kq = (r & 3) * 4;
            float4 v = src[j];
            float s = scl[o], bs = bia[o];
            float y0 = fmaf(v.x, s, bs); y0 = y0 >= 0.f ? y0 : SLOPE * y0;
            float y1 = fmaf(v.y, s, bs); y1 = y1 >= 0.f ? y1 : SLOPE * y1;
            float y2 = fmaf(v.z, s, bs); y2 = y2 >= 0.f ? y2 : SLOPE * y2;
            float y3 = fmaf(v.w, s, bs); y3 = y3 >= 0.f ? y3 : SLOPE * y3;
            float* dst = &x1s[pp][o * XST + kq];
            *(float2*)(dst)     = make_float2(y0, y1);
            *(float2*)(dst + 2) = make_float2(y2, y3);
        }
        __syncthreads();

        // packed score GEMM: S[o][k] = sum_c Ws[o][c] * x1[c][k]
        unsigned long long sL[4] = {0ull, 0ull, 0ull, 0ull};
        unsigned long long sH[4] = {0ull, 0ull, 0ull, 0ull};
        const float* Xp = x1s[p_loc];
        #pragma unroll 2
        for (int c = 0; c < OUT; ++c) {
            unsigned long long x01 = *(const unsigned long long*)&Xp[c * XST + kbase];
            unsigned long long x23 = *(const unsigned long long*)&Xp[c * XST + kbase + 2];
            float4 w = *(const float4*)&Wst[c * WST + obase];
            unsigned long long w0 = dup2(w.x), w1 = dup2(w.y), w2 = dup2(w.z), w3 = dup2(w.w);
            fma2(sL[0], w0, x01); fma2(sH[0], w0, x23);
            fma2(sL[1], w1, x01); fma2(sH[1], w1, x23);
            fma2(sL[2], w2, x01); fma2(sH[2], w2, x23);
            fma2(sL[3], w3, x01); fma2(sH[3], w3, x23);
        }

        // softmax over K + weighted pooling
        #pragma unroll
        for (int jo = 0; jo < 4; ++jo) {
            float s0, s1, s2, s3;
            unpack2(sL[jo], s0, s1);
            unpack2(sH[jo], s2, s3);
            int o = obase + jo;
            float m = fmaxf(fmaxf(s0, s1), fmaxf(s2, s3));
            m = fmaxf(m, __shfl_xor_sync(0xffffffffu, m, 1));
            m = fmaxf(m, __shfl_xor_sync(0xffffffffu, m, 2));
            float e0 = __expf(s0 - m);
            float e1 = __expf(s1 - m);
            float e2 = __expf(s2 - m);
            float e3 = __expf(s3 - m);
            float den = e0 + e1 + e2 + e3;
            const float* xo = &Xp[o * XST + kbase];
            float num = e0 * xo[0] + e1 * xo[1] + e2 * xo[2] + e3 * xo[3];
            den += __shfl_xor_sync(0xffffffffu, den, 1);
            num += __shfl_xor_sync(0xffffffffu, num, 1);
            den += __shfl_xor_sync(0xffffffffu, den, 2);
            num += __shfl_xor_sync(0xffffffffu, num, 2);
            if (kg == 0) ps[p_loc][o] = num / den;
        }
        __syncthreads();

        // z2 = Wm @ p
        {
            int o  = t & 63;
            int pp = t >> 6;
            float z2 = 0.f;
            #pragma unroll 8
            for (int c = 0; c < OUT; ++c)
                z2 = fmaf(Wms[o * 65 + c], ps[pp][c], z2);
            int n = n0 + pair * 2 + pp;
            out[((size_t)b * OUT + o) * N + n] = z2;   // raw pre-BN2
            a2s += z2;
            a2q += z2 * z2;
        }
    }

    int slot = blk & (SLOTS - 1);
    atomicAdd(&g_bn2s[slot][t & 63], a2s);
    atomicAdd(&g_bn2q[slot][t & 63], a2q);
}

// ---------------- kernel 5: BN2 + LeakyReLU in place (vectorized) ----------------
__global__ void k5(float* __restrict__ out) {
    int i = blockIdx.x * blockDim.x + threadIdx.x;
    if (i < B * OUT * N / 4) {
        int o = (i * 4 / N) & (OUT - 1);
        float s = g_scale2[o], bs = g_bias2[o];
        float4 v = ((float4*)out)[i];
        v.x = fmaf(v.x, s, bs); v.x = v.x >= 0.f ? v.x : SLOPE * v.x;
        v.y = fmaf(v.y, s, bs); v.y = v.y >= 0.f ? v.y : SLOPE * v.y;
        v.z = fmaf(v.z, s, bs); v.z = v.z >= 0.f ? v.z : SLOPE * v.z;
        v.w = fmaf(v.w, s, bs); v.w = v.w >= 0.f ? v.w : SLOPE * v.w;
        ((float4*)out)[i] = v;
    }
}

// ---------------- launch ----------------
extern "C" void kernel_launch(void* const* d_in, const int* in_sizes, int n_in,
                              void* d_out, int out_size) {
    const float* xyz  = (const float*)d_in[0];
    const float* feat = (const float*)d_in[1];
    const int*   nidx = (const int*)d_in[2];
    const float* W1   = (const float*)d_in[3];
    const float* g1   = (const float*)d_in[4];
    const float* b1   = (const float*)d_in[5];
    const float* Ws   = (const float*)d_in[6];
    const float* Wm   = (const float*)d_in[7];
    const float* g2   = (const float*)d_in[8];
    const float* b2   = (const float*)d_in[9];
    float* out = (float*)d_out;

    k_zero<<<(SLOTS * OUT + 255) / 256, 256>>>();
    k_trans<<<dim3(N / 32, C / 32, B), dim3(32, 8)>>>(feat);
    k1<<<B * N / PPB1, 128>>>(xyz, nidx, W1);
    k_bnfin1<<<1, OUT>>>(g1, b1);
    k3<<<B * N / PPB3, 128>>>(Ws, Wm, out);
    k_bnfin2<<<1, OUT>>>(g2, b2);
    k5<<<(B * OUT * N / 4 + 255) / 256, 256>>>(out);
}